// round 11
// baseline (speedup 1.0000x reference)
#include <cuda_runtime.h>
#include <cstdint>

#define NQ 4096
#define TPB 256

// Swizzle: s(e) = e ^ ((e>>5 & 7)<<2) ^ ((e>>8 & 1)<<4).
// Bank bits of s(e): {e0, e1, e2^e5, e3^e6, e4^e7^e8}.
// Bijective on [0,4096); XORs only into bits 2-4 -> float4 alignment kept.
__device__ __forceinline__ int s_idx(int e) {
    return e ^ (((e >> 5) & 7) << 2) ^ (((e >> 8) & 1) << 4);
}

__device__ __forceinline__ void butterfly16(float v[16]) {
#pragma unroll
    for (int bs = 1; bs < 16; bs <<= 1) {
#pragma unroll
        for (int i = 0; i < 16; i++) {
            if ((i & bs) == 0) {
                float a = v[i], b = v[i + bs];
                v[i] = a + b;
                v[i + bs] = a - b;
            }
        }
    }
}

// Radix-16^3 core over one row. v[] holds P1 values (regs = dims 8-11).
// STS -> bar -> P2 (dims 0-3, float4, in-place) -> bar -> P3 (dims 4-7) -> STG.
// All smem patterns conflict-free under s_idx (verified R9).
__device__ __forceinline__ void fwht_core(float v[16], float* bufA,
                                          float* __restrict__ yr, int t) {
    butterfly16(v);  // dims 8-11
#pragma unroll
    for (int r = 0; r < 16; r++)
        bufA[s_idx(r * 256 + t)] = v[r];
    __syncthreads();

#pragma unroll
    for (int q = 0; q < 4; q++) {
        float4 f = *reinterpret_cast<const float4*>(bufA + s_idx((t << 4) | (q << 2)));
        v[4 * q + 0] = f.x;
        v[4 * q + 1] = f.y;
        v[4 * q + 2] = f.z;
        v[4 * q + 3] = f.w;
    }
    butterfly16(v);  // dims 0-3
#pragma unroll
    for (int q = 0; q < 4; q++) {
        *reinterpret_cast<float4*>(bufA + s_idx((t << 4) | (q << 2))) =
            make_float4(v[4 * q], v[4 * q + 1], v[4 * q + 2], v[4 * q + 3]);
    }
    __syncthreads();

    const int ebase = (t & 15) | ((t >> 4) << 8);
#pragma unroll
    for (int i = 0; i < 16; i++)
        v[i] = bufA[s_idx(ebase | (i << 4))];
    butterfly16(v);  // dims 4-7
#pragma unroll
    for (int i = 0; i < 16; i++)
        yr[ebase | (i << 4)] = v[i];
}

// Persistent CTAs, rolling 2-stage pipeline: while fwht_core processes row r,
// a cp.async.bulk streams row r+1 into bufB. Keeps each CTA's DRAM-read path
// busy continuously instead of bursting all reads at row start.
__global__ void __launch_bounds__(TPB, 6) fwht4096_persist_kernel(
    const float* __restrict__ x, float* __restrict__ y, int nrows) {
    __shared__ float bufA[NQ];              // exchange buffer (swizzled layout)
    __shared__ alignas(16) float bufB[NQ];  // prefetch target (linear layout)
    __shared__ alignas(8) uint64_t mbar;

    const int t = threadIdx.x;
    const float scale = 0.015625f;  // 1/sqrt(4096)
    float v[16];

    // Contiguous row chunk for this CTA (balanced split).
    const int r0 = (int)((long long)blockIdx.x * nrows / gridDim.x);
    const int r1 = (int)((long long)(blockIdx.x + 1) * nrows / gridDim.x);

    uint32_t mb, sbB;
    asm("{ .reg .u64 a; cvta.to.shared.u64 a, %1; cvt.u32.u64 %0, a; }"
        : "=r"(mb) : "l"(&mbar));
    asm("{ .reg .u64 a; cvta.to.shared.u64 a, %1; cvt.u32.u64 %0, a; }"
        : "=r"(sbB) : "l"(bufB));

    if (t == 0) {
        asm volatile("mbarrier.init.shared.b64 [%0], 1;" :: "r"(mb) : "memory");
        asm volatile("fence.proxy.async.shared::cta;" ::: "memory");
    }
    __syncthreads();  // mbarrier visible to all threads before any wait

    // Prime the pipeline: prefetch first row.
    if (t == 0) {
        asm volatile("mbarrier.arrive.expect_tx.shared.b64 _, [%0], %1;"
                     :: "r"(mb), "r"(NQ * 4) : "memory");
        asm volatile(
            "cp.async.bulk.shared::cluster.global.mbarrier::complete_tx::bytes "
            "[%0], [%1], %2, [%3];"
            :: "r"(sbB), "l"(x + (size_t)r0 * NQ), "r"(NQ * 4), "r"(mb)
            : "memory");
    }

    int p = 0;  // mbarrier phase parity
    for (int r = r0; r < r1; r++) {
        // Wait for row r's data in bufB.
        asm volatile(
            "{\n\t.reg .pred P;\n"
            "W_%=:\n\t"
            "mbarrier.try_wait.parity.shared::cta.b64 P, [%0], %1;\n\t"
            "@!P bra W_%=;\n\t}"
            :: "r"(mb), "r"(p) : "memory");
        p ^= 1;

        // P1 load from linear bufB: e = i*256 + t -> bank t%32, CF.
#pragma unroll
        for (int i = 0; i < 16; i++)
            v[i] = bufB[i * 256 + t] * scale;

        // All threads done reading bufB (and done with bufA P3 reads from the
        // previous iteration) before refill / reuse.
        __syncthreads();

        // Launch prefetch of row r+1 — overlaps the whole core below.
        if (t == 0 && r + 1 < r1) {
            asm volatile("mbarrier.arrive.expect_tx.shared.b64 _, [%0], %1;"
                         :: "r"(mb), "r"(NQ * 4) : "memory");
            asm volatile(
                "cp.async.bulk.shared::cluster.global.mbarrier::complete_tx::bytes "
                "[%0], [%1], %2, [%3];"
                :: "r"(sbB), "l"(x + (size_t)(r + 1) * NQ), "r"(NQ * 4), "r"(mb)
                : "memory");
        }

        fwht_core(v, bufA, y + (size_t)r * NQ, t);
    }
}

extern "C" void kernel_launch(void* const* d_in, const int* in_sizes, int n_in,
                              void* d_out, int out_size) {
    const float* x = (const float*)d_in[0];
    float* y = (float*)d_out;
    const int rows = in_sizes[0] / NQ;  // 8192 rows
    // One full wave: 6 CTAs/SM (33KB smem each) x 152 SMs on GB300.
    int grid = 912;
    if (grid > rows) grid = rows;
    fwht4096_persist_kernel<<<grid, TPB>>>(x, y, rows);
}

// round 12
// speedup vs baseline: 1.0801x; 1.0801x over previous
#include <cuda_runtime.h>
#include <cstdint>

#define NQ 4096
#define TPB 256

// Swizzle: s(e) = e ^ ((e>>5 & 7)<<2) ^ ((e>>8 & 1)<<4).
// Bank bits of s(e): {e0, e1, e2^e5, e3^e6, e4^e7^e8}.
// Bijective on [0,4096); XORs only into bits 2-4 -> float4 alignment kept.
// Conflict-free for all three smem patterns below (verified R9).
__device__ __forceinline__ int s_idx(int e) {
    return e ^ (((e >> 5) & 7) << 2) ^ (((e >> 8) & 1) << 4);
}

__device__ __forceinline__ void butterfly16(float v[16]) {
#pragma unroll
    for (int bs = 1; bs < 16; bs <<= 1) {
#pragma unroll
        for (int i = 0; i < 16; i++) {
            if ((i & bs) == 0) {
                float a = v[i], b = v[i + bs];
                v[i] = a + b;
                v[i + bs] = a - b;
            }
        }
    }
}

// 4096-pt FWHT, one row per CTA, 16 floats per thread (R9 chassis).
//   P1: regs = dims {8-11}, loaded directly from gmem (coalesced LDG.32;
//       default cache policy so input lines stay L2-resident across replays)
//   P2: regs = dims {0-3}, via smem float4 (in-place exchange)
//   P3: regs = dims {4-7}, stored directly to gmem with ST.GLOBAL.CS
//       (evict-first: the 128MB output stream must NOT evict the input from
//        GB300's 126MB L2 — input re-reads then hit L2 on subsequent replays)
__global__ void __launch_bounds__(TPB, 8) fwht4096_kernel(const float* __restrict__ x,
                                                          float* __restrict__ y) {
    __shared__ float sm[NQ];  // 16 KB
    const int t = threadIdx.x;
    const size_t base = (size_t)blockIdx.x * NQ;
    const float scale = 0.015625f;  // 1/sqrt(4096)
    float v[16];

    // ---- P1: v[r] = x[r*256 + t]; 16 coalesced LDG.32, high MLP ----
    const float* xr = x + base + t;
#pragma unroll
    for (int r = 0; r < 16; r++)
        v[r] = xr[r * 256] * scale;
    butterfly16(v);  // dims 8-11

    // STS: e = r*256 + t (lanes vary e0-4 -> conflict-free)
#pragma unroll
    for (int r = 0; r < 16; r++)
        sm[s_idx(r * 256 + t)] = v[r];
    __syncthreads();

    // ---- P2: regs = dims 0-3; float4 at e = 16t+4q (chunks distinct -> CF) ----
#pragma unroll
    for (int q = 0; q < 4; q++) {
        float4 f = *reinterpret_cast<const float4*>(sm + s_idx((t << 4) | (q << 2)));
        v[4 * q + 0] = f.x;
        v[4 * q + 1] = f.y;
        v[4 * q + 2] = f.z;
        v[4 * q + 3] = f.w;
    }
    butterfly16(v);  // dims 0-3
#pragma unroll
    for (int q = 0; q < 4; q++) {
        *reinterpret_cast<float4*>(sm + s_idx((t << 4) | (q << 2))) =
            make_float4(v[4 * q], v[4 * q + 1], v[4 * q + 2], v[4 * q + 3]);
    }
    __syncthreads();

    // ---- P3: regs = dims 4-7; e = (t&15)|(i<<4)|((t>>4)<<8) (banks bijective) ----
    const int ebase = (t & 15) | ((t >> 4) << 8);
#pragma unroll
    for (int i = 0; i < 16; i++)
        v[i] = sm[s_idx(ebase | (i << 4))];
    butterfly16(v);  // dims 4-7

    // ---- Store: 16 x STG.32.CS (evict-first), fully coalesced ----
    float* yr = y + base;
#pragma unroll
    for (int i = 0; i < 16; i++)
        __stcs(yr + (ebase | (i << 4)), v[i]);
}

extern "C" void kernel_launch(void* const* d_in, const int* in_sizes, int n_in,
                              void* d_out, int out_size) {
    const float* x = (const float*)d_in[0];
    float* y = (float*)d_out;
    const int rows = in_sizes[0] / NQ;  // 8192 rows
    fwht4096_kernel<<<rows, TPB>>>(x, y);
}

// round 13
// speedup vs baseline: 1.0808x; 1.0007x over previous
#include <cuda_runtime.h>
#include <cstdint>

#define NQ 4096
#define TPB 256

// Swizzle: s(e) = e ^ ((e>>5 & 7)<<2) ^ ((e>>8 & 1)<<4).
// Bank bits of s(e): {e0, e1, e2^e5, e3^e6, e4^e7^e8}.
// Bijective on [0,4096); XORs only into bits 2-4 -> float4 alignment kept.
// Conflict-free for all three smem patterns below:
//   A (STS):  e = r*256 + t          -> lanes vary e0-4 directly
//   B (f4):   e = 16t + 4q           -> chunk bits {q0^t1, q1^t2, t0^t3}
//   C (LDS):  e = (t&15)|(i<<4)|((t>>4)<<8) -> {t0,t1,t2^i1,t3^i2,i0^i3^t4}
__device__ __forceinline__ int s_idx(int e) {
    return e ^ (((e >> 5) & 7) << 2) ^ (((e >> 8) & 1) << 4);
}

__device__ __forceinline__ void butterfly16(float v[16]) {
#pragma unroll
    for (int bs = 1; bs < 16; bs <<= 1) {
#pragma unroll
        for (int i = 0; i < 16; i++) {
            if ((i & bs) == 0) {
                float a = v[i], b = v[i + bs];
                v[i] = a + b;
                v[i + bs] = a - b;
            }
        }
    }
}

// 4096-pt FWHT, one row per CTA, 16 floats per thread.
//   P1: regs = dims {8-11}, loaded directly from gmem (16 coalesced LDG.32,
//       full 128B line per warp per instruction, 16-deep MLP)
//   P2: regs = dims {0-3}, via one smem exchange (float4, in-place)
//   P3: regs = dims {4-7}, stored directly to gmem (coalesced STG.32)
// Exactly one smem exchange pair + 2 barriers; every leg conflict-free.
// This sits at the measured effective-HBM ceiling (~5.9 TB/s mixed r/w):
// six structural variants (TMA, prefetch, persistent, evict-first) all
// measured wall-equal, so the chassis with best occupancy/simplicity wins.
__global__ void __launch_bounds__(TPB, 8) fwht4096_kernel(const float* __restrict__ x,
                                                          float* __restrict__ y) {
    __shared__ float sm[NQ];  // 16 KB
    const int t = threadIdx.x;
    const size_t base = (size_t)blockIdx.x * NQ;
    const float scale = 0.015625f;  // HAD_SCALE / X_H_SCALE = 1/sqrt(4096)
    float v[16];

    // ---- P1: v[r] = x[r*256 + t] ----
    const float* xr = x + base + t;
#pragma unroll
    for (int r = 0; r < 16; r++)
        v[r] = xr[r * 256] * scale;
    butterfly16(v);  // dims 8-11

    // Pattern A: conflict-free STS
#pragma unroll
    for (int r = 0; r < 16; r++)
        sm[s_idx(r * 256 + t)] = v[r];
    __syncthreads();

    // ---- P2: regs = dims 0-3 (pattern B, float4, in-place) ----
#pragma unroll
    for (int q = 0; q < 4; q++) {
        float4 f = *reinterpret_cast<const float4*>(sm + s_idx((t << 4) | (q << 2)));
        v[4 * q + 0] = f.x;
        v[4 * q + 1] = f.y;
        v[4 * q + 2] = f.z;
        v[4 * q + 3] = f.w;
    }
    butterfly16(v);  // dims 0-3
#pragma unroll
    for (int q = 0; q < 4; q++) {
        *reinterpret_cast<float4*>(sm + s_idx((t << 4) | (q << 2))) =
            make_float4(v[4 * q], v[4 * q + 1], v[4 * q + 2], v[4 * q + 3]);
    }
    __syncthreads();

    // ---- P3: regs = dims 4-7 (pattern C) ----
    const int ebase = (t & 15) | ((t >> 4) << 8);
#pragma unroll
    for (int i = 0; i < 16; i++)
        v[i] = sm[s_idx(ebase | (i << 4))];
    butterfly16(v);  // dims 4-7

    // ---- Store: 16 x STG.32; each instruction covers two full 64B segments ----
    float* yr = y + base;
#pragma unroll
    for (int i = 0; i < 16; i++)
        yr[ebase | (i << 4)] = v[i];
}

extern "C" void kernel_launch(void* const* d_in, const int* in_sizes, int n_in,
                              void* d_out, int out_size) {
    const float* x = (const float*)d_in[0];
    float* y = (float*)d_out;
    const int rows = in_sizes[0] / NQ;  // 8192 rows of 4096
    fwht4096_kernel<<<rows, TPB>>>(x, y);
}